// round 5
// baseline (speedup 1.0000x reference)
#include <cuda_runtime.h>
#include <cuda_fp16.h>
#include <mma.h>

using namespace nvcuda;

#define BB   2
#define LL   2048
#define HH   1024
#define NHH  16
#define HDD  64
#define BL   (BB*LL)   // 4096

// fp16 scratch for projected Q,K,V in head-major layout [B, NH, L, HD]
__device__ __half g_Qh[BB*NHH*LL*HDD];
__device__ __half g_Kh[BB*NHH*LL*HDD];
__device__ __half g_Vh[BB*NHH*LL*HDD];

// ---------------------------------------------------------------------------
// Kernel 1: fused QKV projection.  out = X @ W^T + b  (NT GEMM for wmma).
// Block tile 128x128, K-chunk 32, 8 warps each computing 32x64 (2x4 frags).
// Writes fp16 head-major; Q gets the 1/sqrt(64)=0.125 scale folded in.
// ---------------------------------------------------------------------------
#define P_BM  128
#define P_BN  128
#define P_BK  32
#define P_LDS 40   // 32 + 8 halves pad (80 B, multiple of 16 B for wmma)
#define P_LDC 20   // fp32 staging ld (80 B = multiple of 16 B -- REQUIRED by wmma)

__global__ __launch_bounds__(256)
void proj_kernel(const float* __restrict__ Xq, const float* __restrict__ Xk,
                 const float* __restrict__ Xv,
                 const float* __restrict__ Wq, const float* __restrict__ Wk,
                 const float* __restrict__ Wv,
                 const float* __restrict__ bq, const float* __restrict__ bk,
                 const float* __restrict__ bv)
{
    __shared__ __half sA[P_BM * P_LDS];
    __shared__ __half sB[P_BN * P_LDS];
    __shared__ float  sC[8 * 16 * P_LDC];   // per-warp 16x16 staging

    const int z = blockIdx.z;
    const float* X    = (z == 0) ? Xq : (z == 1) ? Xk : Xv;
    const float* W    = (z == 0) ? Wq : (z == 1) ? Wk : Wv;
    const float* bias = (z == 0) ? bq : (z == 1) ? bk : bv;
    __half*      Out  = (z == 0) ? g_Qh : (z == 1) ? g_Kh : g_Vh;
    const float  scale = (z == 0) ? 0.125f : 1.0f;

    const int m0   = blockIdx.x * P_BM;
    const int n0   = blockIdx.y * P_BN;
    const int tid  = threadIdx.x;
    const int warp = tid >> 5;
    const int lane = tid & 31;
    const int wy   = warp >> 1;   // 0..3 -> 32-row band
    const int wx   = warp & 1;    // 0..1 -> 64-col band

    wmma::fragment<wmma::accumulator, 16, 16, 16, float> acc[2][4];
    #pragma unroll
    for (int i = 0; i < 2; i++)
        #pragma unroll
        for (int j = 0; j < 4; j++)
            wmma::fill_fragment(acc[i][j], 0.0f);

    for (int k0 = 0; k0 < HH; k0 += P_BK) {
        __syncthreads();
        // 128x32 fp32 -> fp16 for both A (X tile) and B (W tile)
        #pragma unroll
        for (int t = 0; t < 4; t++) {
            int idx = tid + t * 256;
            int row = idx >> 3;
            int kq  = (idx & 7) << 2;
            float4 va = *reinterpret_cast<const float4*>(X + (size_t)(m0 + row) * HH + k0 + kq);
            sA[row * P_LDS + kq + 0] = __float2half_rn(va.x);
            sA[row * P_LDS + kq + 1] = __float2half_rn(va.y);
            sA[row * P_LDS + kq + 2] = __float2half_rn(va.z);
            sA[row * P_LDS + kq + 3] = __float2half_rn(va.w);
            float4 vb = *reinterpret_cast<const float4*>(W + (size_t)(n0 + row) * HH + k0 + kq);
            sB[row * P_LDS + kq + 0] = __float2half_rn(vb.x);
            sB[row * P_LDS + kq + 1] = __float2half_rn(vb.y);
            sB[row * P_LDS + kq + 2] = __float2half_rn(vb.z);
            sB[row * P_LDS + kq + 3] = __float2half_rn(vb.w);
        }
        __syncthreads();

        #pragma unroll
        for (int kk = 0; kk < 2; kk++) {
            wmma::fragment<wmma::matrix_a, 16, 16, 16, __half, wmma::row_major> af[2];
            #pragma unroll
            for (int fy = 0; fy < 2; fy++)
                wmma::load_matrix_sync(af[fy], &sA[(wy * 32 + fy * 16) * P_LDS + kk * 16], P_LDS);
            #pragma unroll
            for (int fx = 0; fx < 4; fx++) {
                wmma::fragment<wmma::matrix_b, 16, 16, 16, __half, wmma::col_major> bf;
                wmma::load_matrix_sync(bf, &sB[(wx * 64 + fx * 16) * P_LDS + kk * 16], P_LDS);
                #pragma unroll
                for (int fy = 0; fy < 2; fy++)
                    wmma::mma_sync(acc[fy][fx], af[fy], bf, acc[fy][fx]);
            }
        }
    }

    // Epilogue: stage each 16x16 frag in shared, add bias, scale, scatter to
    // head-major fp16 layout.
    float* patch = &sC[warp * 16 * P_LDC];
    #pragma unroll
    for (int fy = 0; fy < 2; fy++) {
        #pragma unroll
        for (int fx = 0; fx < 4; fx++) {
            wmma::store_matrix_sync(patch, acc[fy][fx], P_LDC, wmma::mem_row_major);
            __syncwarp();
            int r  = lane >> 1;
            int c0 = (lane & 1) * 8;
            int m  = m0 + wy * 32 + fy * 16 + r;
            int bidx = m >> 11;      // / 2048
            int l    = m & 2047;
            #pragma unroll
            for (int j = 0; j < 8; j++) {
                int n  = n0 + wx * 64 + fx * 16 + c0 + j;
                int hh = n >> 6;
                int dd = n & 63;
                float v = (patch[r * P_LDC + c0 + j] + bias[n]) * scale;
                Out[(((size_t)(bidx * NHH + hh)) * LL + l) * HDD + dd] = __float2half_rn(v);
            }
            __syncwarp();
        }
    }
}

// ---------------------------------------------------------------------------
// Kernel 2: flash attention.  One block per (b, h, 128-row q tile).
// 8 warps; warp w owns q-rows [16w, 16w+16) end-to-end (S, softmax, PV),
// so softmax needs no cross-warp reduction.  Key tiles of 64, 32 iterations.
// O accumulated in shared fp32 via wmma C-fragment round trips.
// ---------------------------------------------------------------------------
#define A_QT 128
#define A_KT 64
#define LDS_S 68   // float ld (272 B, multiple of 16 B)
#define LDS_H 72   // half  ld (144 B, multiple of 16 B)

#define SMEM2_BYTES ((128*LDS_S + 128*LDS_S + 64) * 4 + \
                     (128*LDS_H + 64*LDS_H + 64*LDS_H + 128*LDS_H) * 2)

__global__ __launch_bounds__(256)
void attn_kernel(const float* __restrict__ mask, float* __restrict__ out)
{
    extern __shared__ char smem[];
    float*  sS    = reinterpret_cast<float*>(smem);      // 128 x 68
    float*  sO    = sS + 128 * LDS_S;                    // 128 x 68
    float*  sMask = sO + 128 * LDS_S;                    // 64
    __half* sQ    = reinterpret_cast<__half*>(sMask + 64);  // 128 x 72
    __half* sK    = sQ + 128 * LDS_H;                    // 64 x 72
    __half* sV    = sK + 64  * LDS_H;                    // 64 x 72
    __half* sP    = sV + 64  * LDS_H;                    // 128 x 72

    const int qt = blockIdx.x, h = blockIdx.y, b = blockIdx.z;
    const int tid = threadIdx.x, warp = tid >> 5, lane = tid & 31;

    const __half* Qg = g_Qh + (((size_t)(b * NHH + h)) * LL + qt * A_QT) * HDD;
    const __half* Kg = g_Kh + ((size_t)(b * NHH + h)) * LL * HDD;
    const __half* Vg = g_Vh + ((size_t)(b * NHH + h)) * LL * HDD;

    for (int i = tid; i < 128 * LDS_S; i += 256) sO[i] = 0.0f;

    #pragma unroll
    for (int t = 0; t < 4; t++) {
        int idx = tid + t * 256;
        int row = idx >> 3, d = (idx & 7) << 3;
        *reinterpret_cast<uint4*>(&sQ[row * LDS_H + d]) =
            *reinterpret_cast<const uint4*>(Qg + row * HDD + d);
    }

    const int rowk  = warp * 16 + (lane >> 1);   // this lane's q-row
    const int cbase = (lane & 1) * 32;           // half-row of 64 keys
    float m_r = -1e30f, l_r = 0.0f;

    for (int kb = 0; kb < LL; kb += A_KT) {
        __syncthreads();   // previous PV done before K/V overwrite
        #pragma unroll
        for (int t = 0; t < 2; t++) {
            int idx = tid + t * 256;
            int row = idx >> 3, d = (idx & 7) << 3;
            *reinterpret_cast<uint4*>(&sK[row * LDS_H + d]) =
                *reinterpret_cast<const uint4*>(Kg + (size_t)(kb + row) * HDD + d);
            *reinterpret_cast<uint4*>(&sV[row * LDS_H + d]) =
                *reinterpret_cast<const uint4*>(Vg + (size_t)(kb + row) * HDD + d);
        }
        if (tid < A_KT)
            sMask[tid] = (1.0f - mask[(size_t)b * LL + kb + tid]) * -10000.0f;
        __syncthreads();

        // ---- S = Q K^T for this warp's 16 rows x 64 keys ----
        wmma::fragment<wmma::accumulator, 16, 16, 16, float> sacc[4];
        #pragma unroll
        for (int fx = 0; fx < 4; fx++) wmma::fill_fragment(sacc[fx], 0.0f);
        #pragma unroll
        for (int kk = 0; kk < 4; kk++) {
            wmma::fragment<wmma::matrix_a, 16, 16, 16, __half, wmma::row_major> af;
            wmma::load_matrix_sync(af, &sQ[(warp * 16) * LDS_H + kk * 16], LDS_H);
            #pragma unroll
            for (int fx = 0; fx < 4; fx++) {
                wmma::fragment<wmma::matrix_b, 16, 16, 16, __half, wmma::col_major> bf;
                wmma::load_matrix_sync(bf, &sK[(fx * 16) * LDS_H + kk * 16], LDS_H);
                wmma::mma_sync(sacc[fx], af, bf, sacc[fx]);
            }
        }
        #pragma unroll
        for (int fx = 0; fx < 4; fx++)
            wmma::store_matrix_sync(&sS[(warp * 16) * LDS_S + fx * 16], sacc[fx],
                                    LDS_S, wmma::mem_row_major);
        __syncwarp();

        // ---- online softmax: 2 lanes per row, 32 cols each ----
        float vals[32];
        float vmax = -1e30f;
        #pragma unroll
        for (int c = 0; c < 32; c++) {
            float v = sS[rowk * LDS_S + cbase + c] + sMask[cbase + c];
            vals[c] = v;
            vmax = fmaxf(vmax, v);
        }
        vmax = fmaxf(vmax, __shfl_xor_sync(0xffffffffu, vmax, 1));
        float m_new = fmaxf(m_r, vmax);
        float alpha = __expf(m_r - m_new);
        float ssum = 0.0f;
        #pragma unroll
        for (int c = 0; c < 32; c++) {
            float p = __expf(vals[c] - m_new);
            ssum += p;
            sP[rowk * LDS_H + cbase + c] = __float2half_rn(p);
        }
        ssum += __shfl_xor_sync(0xffffffffu, ssum, 1);
        l_r = l_r * alpha + ssum;
        m_r = m_new;
        #pragma unroll
        for (int c = 0; c < 32; c++)
            sO[rowk * LDS_S + cbase + c] *= alpha;
        __syncwarp();

        // ---- O += P V ----
        wmma::fragment<wmma::matrix_a, 16, 16, 16, __half, wmma::row_major> pf[4];
        #pragma unroll
        for (int kk = 0; kk < 4; kk++)
            wmma::load_matrix_sync(pf[kk], &sP[(warp * 16) * LDS_H + kk * 16], LDS_H);
        #pragma unroll
        for (int fx = 0; fx < 4; fx++) {
            wmma::fragment<wmma::accumulator, 16, 16, 16, float> oacc;
            wmma::load_matrix_sync(oacc, &sO[(warp * 16) * LDS_S + fx * 16],
                                   LDS_S, wmma::mem_row_major);
            #pragma unroll
            for (int kk = 0; kk < 4; kk++) {
                wmma::fragment<wmma::matrix_b, 16, 16, 16, __half, wmma::row_major> vf;
                wmma::load_matrix_sync(vf, &sV[(kk * 16) * LDS_H + fx * 16], LDS_H);
                wmma::mma_sync(oacc, pf[kk], vf, oacc);
            }
            wmma::store_matrix_sync(&sO[(warp * 16) * LDS_S + fx * 16], oacc,
                                    LDS_S, wmma::mem_row_major);
        }
    }
    __syncwarp();

    // ---- epilogue: out[b, l, h*64 + d] = O / l ----
    float inv = 1.0f / l_r;
    int l = qt * A_QT + rowk;
    float* op = out + ((size_t)b * LL + l) * HH + h * HDD;
    #pragma unroll
    for (int c = 0; c < 32; c++)
        op[cbase + c] = sO[rowk * LDS_S + cbase + c] * inv;
}

// ---------------------------------------------------------------------------
extern "C" void kernel_launch(void* const* d_in, const int* in_sizes, int n_in,
                              void* d_out, int out_size)
{
    const float* query    = (const float*)d_in[0];
    const float* key      = (const float*)d_in[1];
    const float* value    = (const float*)d_in[2];
    const float* key_mask = (const float*)d_in[3];
    const float* Wq       = (const float*)d_in[4];
    const float* bq       = (const float*)d_in[5];
    const float* Wk       = (const float*)d_in[6];
    const float* bk       = (const float*)d_in[7];
    const float* Wv       = (const float*)d_in[8];
    const float* bv       = (const float*)d_in[9];
    float* out            = (float*)d_out;

    cudaFuncSetAttribute(attn_kernel,
                         cudaFuncAttributeMaxDynamicSharedMemorySize,
                         SMEM2_BYTES);

    dim3 g1(BL / P_BM, HH / P_BN, 3);       // 32 x 8 x 3
    proj_kernel<<<g1, 256>>>(query, key, value, Wq, Wk, Wv, bq, bk, bv);

    dim3 g2(LL / A_QT, NHH, BB);            // 16 x 16 x 2
    attn_kernel<<<g2, 256, SMEM2_BYTES>>>(key_mask, out);
}

// round 14
// speedup vs baseline: 1.7838x; 1.7838x over previous
#include <cuda_runtime.h>
#include <cuda_fp16.h>
#include <cstdint>
#include <mma.h>

using namespace nvcuda;

constexpr int cBB  = 2;
constexpr int cLL  = 2048;
constexpr int cHH  = 1024;
constexpr int cNHH = 16;
constexpr int cHDD = 64;
constexpr int cBL  = cBB * cLL;   // 4096

// fp16 scratch for projected Q,K,V in head-major layout [B, NH, L, HD]
__device__ __half g_Qh[cBB*cNHH*cLL*cHDD];
__device__ __half g_Kh[cBB*cNHH*cLL*cHDD];
__device__ __half g_Vh[cBB*cNHH*cLL*cHDD];

// ---------------------------------------------------------------------------
// Kernel 1: fused QKV projection (same algorithm as passing R5 baseline).
// ---------------------------------------------------------------------------
constexpr int cPBM  = 128;
constexpr int cPBN  = 128;
constexpr int cPBK  = 32;
constexpr int cPLDS = 40;   // 80 B, multiple of 16 B for wmma
constexpr int cPLDC = 20;   // 80 B, multiple of 16 B -- REQUIRED by wmma

__global__ __launch_bounds__(256)
void proj_kernel(const float* __restrict__ Xq, const float* __restrict__ Xk,
                 const float* __restrict__ Xv,
                 const float* __restrict__ Wq, const float* __restrict__ Wk,
                 const float* __restrict__ Wv,
                 const float* __restrict__ bq, const float* __restrict__ bk,
                 const float* __restrict__ bv)
{
    __shared__ __half sA[cPBM * cPLDS];
    __shared__ __half sB[cPBN * cPLDS];
    __shared__ float  sC[8 * 16 * cPLDC];

    const int z = blockIdx.z;
    const float* X    = (z == 0) ? Xq : (z == 1) ? Xk : Xv;
    const float* W    = (z == 0) ? Wq : (z == 1) ? Wk : Wv;
    const float* bias = (z == 0) ? bq : (z == 1) ? bk : bv;
    __half*      Out  = (z == 0) ? g_Qh : (z == 1) ? g_Kh : g_Vh;
    const float  scale = (z == 0) ? 0.125f : 1.0f;

    const int m0   = blockIdx.x * cPBM;
    const int n0   = blockIdx.y * cPBN;
    const int tid  = threadIdx.x;
    const int warp = tid >> 5;
    const int lane = tid & 31;
    const int wy   = warp >> 1;
    const int wx   = warp & 1;

    wmma::fragment<wmma::accumulator, 16, 16, 16, float> acc[2][4];
    #pragma unroll
    for (int i = 0; i < 2; i++)
        #pragma unroll
        for (int j = 0; j < 4; j++)
            wmma::fill_fragment(acc[i][j], 0.0f);

    for (int k0 = 0; k0 < cHH; k0 += cPBK) {
        __syncthreads();
        #pragma unroll
        for (int t = 0; t < 4; t++) {
            int idx = tid + t * 256;
            int row = idx >> 3;
            int kq  = (idx & 7) << 2;
            float4 va = *reinterpret_cast<const float4*>(X + (size_t)(m0 + row) * cHH + k0 + kq);
            sA[row * cPLDS + kq + 0] = __float2half_rn(va.x);
            sA[row * cPLDS + kq + 1] = __float2half_rn(va.y);
            sA[row * cPLDS + kq + 2] = __float2half_rn(va.z);
            sA[row * cPLDS + kq + 3] = __float2half_rn(va.w);
            float4 vb = *reinterpret_cast<const float4*>(W + (size_t)(n0 + row) * cHH + k0 + kq);
            sB[row * cPLDS + kq + 0] = __float2half_rn(vb.x);
            sB[row * cPLDS + kq + 1] = __float2half_rn(vb.y);
            sB[row * cPLDS + kq + 2] = __float2half_rn(vb.z);
            sB[row * cPLDS + kq + 3] = __float2half_rn(vb.w);
        }
        __syncthreads();

        #pragma unroll
        for (int kk = 0; kk < 2; kk++) {
            wmma::fragment<wmma::matrix_a, 16, 16, 16, __half, wmma::row_major> af[2];
            #pragma unroll
            for (int fy = 0; fy < 2; fy++)
                wmma::load_matrix_sync(af[fy], &sA[(wy * 32 + fy * 16) * cPLDS + kk * 16], cPLDS);
            #pragma unroll
            for (int fx = 0; fx < 4; fx++) {
                wmma::fragment<wmma::matrix_b, 16, 16, 16, __half, wmma::col_major> bf;
                wmma::load_matrix_sync(bf, &sB[(wx * 64 + fx * 16) * cPLDS + kk * 16], cPLDS);
                #pragma unroll
                for (int fy = 0; fy < 2; fy++)
                    wmma::mma_sync(acc[fy][fx], af[fy], bf, acc[fy][fx]);
            }
        }
    }

    float* patch = &sC[warp * 16 * cPLDC];
    #pragma unroll
    for (int fy = 0; fy < 2; fy++) {
        #pragma unroll
        for (int fx = 0; fx < 4; fx++) {
            wmma::store_matrix_sync(patch, acc[fy][fx], cPLDC, wmma::mem_row_major);
            __syncwarp();
            int r  = lane >> 1;
            int c0 = (lane & 1) * 8;
            int m  = m0 + wy * 32 + fy * 16 + r;
            int bidx = m >> 11;
            int l    = m & 2047;
            #pragma unroll
            for (int j = 0; j < 8; j++) {
                int n  = n0 + wx * 64 + fx * 16 + c0 + j;
                int hh = n >> 6;
                int dd = n & 63;
                float v = (patch[r * cPLDC + c0 + j] + bias[n]) * scale;
                Out[(((size_t)(bidx * cNHH + hh)) * cLL + l) * cHDD + dd] = __float2half_rn(v);
            }
            __syncwarp();
        }
    }
}

// ---------------------------------------------------------------------------
// Kernel 2: register-resident flash attention with raw mma.sync.m16n8k16.
// One block (8 warps) per (b, h, 128-row q tile).  Warp w owns q-rows
// [16w,16w+16).  Q fragments loaded once; S, softmax, P, O all in registers.
// K/V double-buffered in smem via cp.async; ldmatrix feeds the mma operands.
// K uses NON-trans ldmatrix; V uses trans ldmatrix.
// NOTE: braces inside asm strings are written as hex escapes so the source
// text contains no literal brace characters inside string literals.
// ---------------------------------------------------------------------------
constexpr int cANT  = cLL / 64;   // 32 key tiles of 64
constexpr int cKVLD = 72;         // half stride (144 B)

// smem: sQ 128x72 | sK 2x64x72 | sV 2x64x72 (halves) | sMask 2x64 (float)
constexpr int cSMEM2 = (128*cKVLD + 2*64*cKVLD + 2*64*cKVLD) * 2 + 2*64*4;

__device__ __forceinline__ uint32_t s2u(const void* p) {
    return (uint32_t)__cvta_generic_to_shared(p);
}
__device__ __forceinline__ void cp16(uint32_t dst, const void* src) {
    asm volatile("cp.async.cg.shared.global [%0], [%1], 16;" : : "r"(dst), "l"(src));
}
__device__ __forceinline__ void ldmx4(uint32_t* r, uint32_t addr) {
    asm volatile("ldmatrix.sync.aligned.m8n8.x4.shared.b16 \x7b%0,%1,%2,%3\x7d, [%4];"
        : "=r"(r[0]), "=r"(r[1]), "=r"(r[2]), "=r"(r[3]) : "r"(addr));
}
__device__ __forceinline__ void ldmx4t(uint32_t* r, uint32_t addr) {
    asm volatile("ldmatrix.sync.aligned.m8n8.x4.trans.shared.b16 \x7b%0,%1,%2,%3\x7d, [%4];"
        : "=r"(r[0]), "=r"(r[1]), "=r"(r[2]), "=r"(r[3]) : "r"(addr));
}
__device__ __forceinline__ void mma16816(float* c, const uint32_t* a, const uint32_t* b) {
    asm volatile("mma.sync.aligned.m16n8k16.row.col.f32.f16.f16.f32 "
        "\x7b%0,%1,%2,%3\x7d,\x7b%4,%5,%6,%7\x7d,\x7b%8,%9\x7d,\x7b%0,%1,%2,%3\x7d;"
        : "+f"(c[0]), "+f"(c[1]), "+f"(c[2]), "+f"(c[3])
        : "r"(a[0]), "r"(a[1]), "r"(a[2]), "r"(a[3]), "r"(b[0]), "r"(b[1]));
}
__device__ __forceinline__ void cpcommit() {
    asm volatile("cp.async.commit_group;" : :);
}
__device__ __forceinline__ void cpwait0() {
    asm volatile("cp.async.wait_group 0;" : :);
}

__global__ __launch_bounds__(256, 2)
void attn_kernel(const float* __restrict__ mask, float* __restrict__ out)
{
    extern __shared__ char smem[];
    __half* sQ = reinterpret_cast<__half*>(smem);        // 128 x 72
    __half* sK = sQ + 128 * cKVLD;                       // 2 x 64 x 72
    __half* sV = sK + 2 * 64 * cKVLD;                    // 2 x 64 x 72
    float*  sM = reinterpret_cast<float*>(sV + 2 * 64 * cKVLD);  // 2 x 64

    const int qt = blockIdx.x;
    const int h  = blockIdx.y;
    const int b  = blockIdx.z;
    const int tid = threadIdx.x;
    const int warp = tid >> 5;
    const int lane = tid & 31;
    const int g  = lane >> 2;     // row-in-16 group
    const int t4 = lane & 3;      // col pair selector

    const __half* Qg = g_Qh + (((size_t)(b * cNHH + h)) * cLL + qt * 128) * cHDD;
    const __half* Kg = g_Kh + ((size_t)(b * cNHH + h)) * cLL * cHDD;
    const __half* Vg = g_Vh + ((size_t)(b * cNHH + h)) * cLL * cHDD;
    const float*  Mg = mask + (size_t)b * cLL;

    // stage Q tile (128 x 64 halves)
    #pragma unroll
    for (int t = 0; t < 4; t++) {
        int idx = tid + t * 256;
        int row = idx >> 3;
        int d = (idx & 7) << 3;
        *reinterpret_cast<uint4*>(&sQ[row * cKVLD + d]) =
            *reinterpret_cast<const uint4*>(Qg + row * cHDD + d);
    }
    // cp.async K/V/mask tile 0 into buffer 0
    #pragma unroll
    for (int t = 0; t < 2; t++) {
        int idx = tid + t * 256;
        int row = idx >> 3;
        int d = (idx & 7) << 3;
        cp16(s2u(&sK[row * cKVLD + d]), Kg + row * cHDD + d);
        cp16(s2u(&sV[row * cKVLD + d]), Vg + row * cHDD + d);
    }
    if (tid < 16) cp16(s2u(&sM[tid * 4]), Mg + tid * 4);
    cpcommit();
    __syncthreads();   // sQ visible to ldmatrix

    // Q a-fragments (held whole kernel): qa[kt] covers d = 16kt..16kt+15
    uint32_t qa[4][4];
    {
        const __half* qb = sQ + warp * 16 * cKVLD;
        #pragma unroll
        for (int kt = 0; kt < 4; kt++)
            ldmx4(qa[kt], s2u(qb + (lane & 15) * cKVLD + kt * 16 + (lane >> 4) * 8));
    }

    float oacc[8][4];
    #pragma unroll
    for (int n = 0; n < 8; n++) {
        oacc[n][0] = 0.0f; oacc[n][1] = 0.0f; oacc[n][2] = 0.0f; oacc[n][3] = 0.0f;
    }
    float m0 = -1e30f, m1 = -1e30f, l0 = 0.0f, l1 = 0.0f;

    for (int kb = 0; kb < cANT; kb++) {
        const int buf = kb & 1;
        cpwait0();
        __syncthreads();   // tile kb resident; prior reads of other buffer done

        if (kb + 1 < cANT) {
            const __half* Kn = Kg + (size_t)(kb + 1) * 64 * cHDD;
            const __half* Vn = Vg + (size_t)(kb + 1) * 64 * cHDD;
            __half* dK = sK + (buf ^ 1) * 64 * cKVLD;
            __half* dV = sV + (buf ^ 1) * 64 * cKVLD;
            #pragma unroll
            for (int t = 0; t < 2; t++) {
                int idx = tid + t * 256;
                int row = idx >> 3;
                int d = (idx & 7) << 3;
                cp16(s2u(&dK[row * cKVLD + d]), Kn + row * cHDD + d);
                cp16(s2u(&dV[row * cKVLD + d]), Vn + row * cHDD + d);
            }
            if (tid < 16)
                cp16(s2u(&sM[(buf ^ 1) * 64 + tid * 4]), Mg + (kb + 1) * 64 + tid * 4);
            cpcommit();
        }

        const __half* Kb = sK + buf * 64 * cKVLD;
        const __half* Vb = sV + buf * 64 * cKVLD;
        const float*  Mb = sM + buf * 64;

        // ---- S = Q K^T : 8 n-tiles of 8 keys (K fragments: NON-trans) ----
        float sacc[8][4];
        #pragma unroll
        for (int n = 0; n < 8; n++) {
            sacc[n][0] = 0.0f; sacc[n][1] = 0.0f; sacc[n][2] = 0.0f; sacc[n][3] = 0.0f;
            uint32_t fk0[4];
            uint32_t fk1[4];
            ldmx4(fk0, s2u(Kb + (n * 8 + (lane & 7)) * cKVLD + (lane >> 3) * 8));
            ldmx4(fk1, s2u(Kb + (n * 8 + (lane & 7)) * cKVLD + 32 + (lane >> 3) * 8));
            mma16816(sacc[n], qa[0], fk0 + 0);
            mma16816(sacc[n], qa[1], fk0 + 2);
            mma16816(sacc[n], qa[2], fk1 + 0);
            mma16816(sacc[n], qa[3], fk1 + 2);
        }

        // ---- mask + row max (rows g and g+8; 4 lanes share a row) ----
        float vmax0 = -1e30f, vmax1 = -1e30f;
        #pragma unroll
        for (int n = 0; n < 8; n++) {
            float mka = fmaf(Mb[n * 8 + t4 * 2 + 0], 10000.0f, -10000.0f);
            float mkb = fmaf(Mb[n * 8 + t4 * 2 + 1], 10000.0f, -10000.0f);
            sacc[n][0] += mka; sacc[n][1] += mkb;
            sacc[n][2] += mka; sacc[n][3] += mkb;
            vmax0 = fmaxf(vmax0, fmaxf(sacc[n][0], sacc[n][1]));
            vmax1 = fmaxf(vmax1, fmaxf(sacc[n][2], sacc[n][3]));
        }
        vmax0 = fmaxf(vmax0, __shfl_xor_sync(0xffffffffu, vmax0, 1));
        vmax0 = fmaxf(vmax0, __shfl_xor_sync(0xffffffffu, vmax0, 2));
        vmax1 = fmaxf(vmax1, __shfl_xor_sync(0xffffffffu, vmax1, 1));
        vmax1 = fmaxf(vmax1, __shfl_xor_sync(0xffffffffu, vmax1, 2));
        float mn0 = fmaxf(m0, vmax0);
        float mn1 = fmaxf(m1, vmax1);
        float al0 = __expf(m0 - mn0);
        float al1 = __expf(m1 - mn1);

        // ---- exp -> P (fp16 A-fragments, in registers) + row sums ----
        float s0 = 0.0f, s1 = 0.0f;
        uint32_t pa[4][4];
        #pragma unroll
        for (int n = 0; n < 8; n++) {
            float p0 = __expf(sacc[n][0] - mn0);
            float p1 = __expf(sacc[n][1] - mn0);
            float p2 = __expf(sacc[n][2] - mn1);
            float p3 = __expf(sacc[n][3] - mn1);
            s0 += p0 + p1;
            s1 += p2 + p3;
            __half2 hA = __floats2half2_rn(p0, p1);
            __half2 hB = __floats2half2_rn(p2, p3);
            int kt = n >> 1;
            int hi = (n & 1) * 2;
            pa[kt][hi + 0] = *reinterpret_cast<uint32_t*>(&hA);
            pa[kt][hi + 1] = *reinterpret_cast<uint32_t*>(&hB);
        }
        s0 += __shfl_xor_sync(0xffffffffu, s0, 1);
        s0 += __shfl_xor_sync(0xffffffffu, s0, 2);
        s1 += __shfl_xor_sync(0xffffffffu, s1, 1);
        s1 += __shfl_xor_sync(0xffffffffu, s1, 2);
        l0 = l0 * al0 + s0;
        l1 = l1 * al1 + s1;
        m0 = mn0;
        m1 = mn1;

        // ---- rescale O, then O += P V (V fragments: trans) ----
        #pragma unroll
        for (int n = 0; n < 8; n++) {
            oacc[n][0] *= al0; oacc[n][1] *= al0;
            oacc[n][2] *= al1; oacc[n][3] *= al1;
        }
        #pragma unroll
        for (int n = 0; n < 8; n++) {
            uint32_t fv0[4];
            uint32_t fv1[4];
            ldmx4t(fv0, s2u(Vb + lane * cKVLD + n * 8));
            ldmx4t(fv1, s2u(Vb + (32 + lane) * cKVLD + n * 8));
            mma16816(oacc[n], pa[0], fv0 + 0);
            mma16816(oacc[n], pa[1], fv0 + 2);
            mma16816(oacc[n], pa[2], fv1 + 0);
            mma16816(oacc[n], pa[3], fv1 + 2);
        }
    }

    // ---- epilogue: out[b, row, h*64 + d] = O / l ----
    float inv0 = 1.0f / l0;
    float inv1 = 1.0f / l1;
    int row0 = qt * 128 + warp * 16 + g;
    float* o0 = out + ((size_t)b * cLL + row0) * cHH + h * cHDD;
    float* o1 = o0 + 8 * cHH;
    #pragma unroll
    for (int n = 0; n < 8; n++) {
        int c = n * 8 + t4 * 2;
        float2 v0 = make_float2(oacc[n][0] * inv0, oacc[n][1] * inv0);
        float2 v1 = make_float2(oacc[n][2] * inv1, oacc[n][3] * inv1);
        *reinterpret_cast<float2*>(o0 + c) = v0;
        *reinterpret_cast<float2*>(o1 + c) = v1;
    }
}

// ---------------------------------------------------------------------------
extern "C" void kernel_launch(void* const* d_in, const int* in_sizes, int n_in,
                              void* d_out, int out_size)
{
    const float* query    = (const float*)d_in[0];
    const float* key      = (const float*)d_in[1];
    const float* value    = (const float*)d_in[2];
    const float* key_mask = (const float*)d_in[3];
    const float* Wq       = (const float*)d_in[4];
    const float* bq       = (const float*)d_in[5];
    const float* Wk       = (const float*)d_in[6];
    const float* bk       = (const float*)d_in[7];
    const float* Wv       = (const float*)d_in[8];
    const float* bv       = (const float*)d_in[9];
    float* out            = (float*)d_out;

    cudaFuncSetAttribute(attn_kernel,
                         cudaFuncAttributeMaxDynamicSharedMemorySize,
                         cSMEM2);

    dim3 g1(cBL / cPBM, cHH / cPBN, 3);     // 32 x 8 x 3
    proj_kernel<<<g1, 256>>>(query, key, value, Wq, Wk, Wv, bq, bk, bv);

    dim3 g2(cLL / 128, cNHH, cBB);          // 16 x 16 x 2
    attn_kernel<<<g2, 256, cSMEM2>>>(key_mask, out);
}